// round 5
// baseline (speedup 1.0000x reference)
#include <cuda_runtime.h>

// Problem constants
#define B_  8
#define N_  1024
#define C_  64
#define O_  64
#define KM  4          // K+1
#define BN  (B_*N_)    // 8192

// -------- device scratch (no allocations allowed) --------
__device__ float g_sRi[BN], g_sIi[BN], g_sRj[BN], g_sIj[BN];
__device__ float g_rsum[BN];                 // 1 / sum_i exp(mag[b,i,j]) per (b,j)
__device__ float g_rowR[KM*BN], g_rowI[KM*BN];  // (b*4+m)*N + i

// ============================================================
// Kernel 1: per-(b,n) attention projections. One warp per (b,n).
// ============================================================
__global__ void __launch_bounds__(256) k1_proj(
    const float* __restrict__ Xr, const float* __restrict__ Xi,
    const float* __restrict__ awr, const float* __restrict__ awi,
    const float* __restrict__ abr, const float* __restrict__ abi)
{
    int warp = (blockIdx.x * blockDim.x + threadIdx.x) >> 5;
    int lane = threadIdx.x & 31;
    if (warp >= BN) return;
    const float* xr = Xr + warp * C_;
    const float* xi = Xi + warp * C_;
    float sRi = 0.f, sIi = 0.f, sRj = 0.f, sIj = 0.f;
#pragma unroll
    for (int t = 0; t < 2; t++) {
        int c = lane + t * 32;
        float a = xr[c], b = xi[c];
        float wri = awr[c],      wii = awi[c];
        float wrj = awr[C_ + c], wij = awi[C_ + c];
        sRi += a * wri - b * wii;
        sIi += a * wii + b * wri;
        sRj += a * wrj - b * wij;
        sIj += a * wij + b * wrj;
    }
#pragma unroll
    for (int off = 16; off; off >>= 1) {
        sRi += __shfl_xor_sync(0xffffffffu, sRi, off);
        sIi += __shfl_xor_sync(0xffffffffu, sIi, off);
        sRj += __shfl_xor_sync(0xffffffffu, sRj, off);
        sIj += __shfl_xor_sync(0xffffffffu, sIj, off);
    }
    if (lane == 0) {
        g_sRi[warp] = sRi + abr[0];
        g_sIi[warp] = sIi + abi[0];
        g_sRj[warp] = sRj;
        g_sIj[warp] = sIj;
    }
}

// ============================================================
// Kernel 2: softmax denominator per (b,j): sum over i of exp(mag).
// mag is bounded (<~8) so no max-subtraction needed (identical math).
// ============================================================
__global__ void __launch_bounds__(128) k2_sumexp(
    const float* __restrict__ par, const float* __restrict__ pai)
{
    int bj = blockIdx.x;          // b*N + j
    int b  = bj >> 10;
    float sRj = g_sRj[bj], sIj = g_sIj[bj];
    float a_r = par[0], a_i = pai[0];
    const float* sRi = g_sRi + (b << 10);
    const float* sIi = g_sIi + (b << 10);
    float acc = 0.f;
#pragma unroll
    for (int t = 0; t < N_ / 128; t++) {
        int i = threadIdx.x + t * 128;
        float sr = sRi[i] + sRj;
        float si = sIi[i] + sIj;
        float pr = sr >= 0.f ? sr : a_r * sr;
        float pi = si >= 0.f ? si : a_i * si;
        float r2 = pr * pr + pi * pi;
        float inv = rsqrtf(fmaxf(r2, 1e-30f));
        float mag = r2 * inv;
        acc += __expf(mag);
    }
    __shared__ float sred[4];
#pragma unroll
    for (int off = 16; off; off >>= 1) acc += __shfl_xor_sync(0xffffffffu, acc, off);
    if ((threadIdx.x & 31) == 0) sred[threadIdx.x >> 5] = acc;
    __syncthreads();
    if (threadIdx.x == 0) {
        float t = sred[0] + sred[1] + sred[2] + sred[3];
        g_rsum[bj] = 1.f / t;
    }
}

// ============================================================
// Kernel 3 (dominant, HBM-bound): one block per (b,i) row.
// Streams L_real/L_imag exactly once (268 MB) -> rowR/rowI.
// ============================================================
__global__ void __launch_bounds__(256) k3_main(
    const float* __restrict__ Lr, const float* __restrict__ Li,
    const float* __restrict__ par, const float* __restrict__ pai)
{
    int bi = blockIdx.x;          // b*N + i
    int b  = bi >> 10;
    int i  = bi & 1023;
    int tid = threadIdx.x;
    int j0 = tid * 4;

    float sRi = g_sRi[bi], sIi = g_sIi[bi];
    float a_r = par[0], a_i = pai[0];

    const int bj0 = (b << 10) + j0;
    float4 sRj4 = *(const float4*)(g_sRj + bj0);
    float4 sIj4 = *(const float4*)(g_sIj + bj0);
    float4 rs4  = *(const float4*)(g_rsum + bj0);
    float sRjv[4] = {sRj4.x, sRj4.y, sRj4.z, sRj4.w};
    float sIjv[4] = {sIj4.x, sIj4.y, sIj4.z, sIj4.w};
    float rsv [4] = {rs4.x,  rs4.y,  rs4.z,  rs4.w };

    float ar[4], ai[4];
#pragma unroll
    for (int k = 0; k < 4; k++) {
        float sr = sRi + sRjv[k];
        float si = sIi + sIjv[k];
        float pr = sr >= 0.f ? sr : a_r * sr;
        float pi = si >= 0.f ? si : a_i * si;
        float r2 = pr * pr + pi * pi;
        float inv = rsqrtf(fmaxf(r2, 1e-30f));
        float mag = r2 * inv;
        float e = __expf(mag);
        float sc = e * inv * rsv[k];
        ar[k] = sc * pr;
        ai[k] = sc * pi;
    }

    float accR[4], accI[4];
#pragma unroll
    for (int m = 0; m < 4; m++) { accR[m] = 0.f; accI[m] = 0.f; }

#pragma unroll
    for (int m = 0; m < 4; m++) {
        size_t base = ((size_t)((b * 4 + m) * N_ + i)) * N_ + j0;
        float4 lr = *(const float4*)(Lr + base);
        float4 li = *(const float4*)(Li + base);
        accR[m] += lr.x * ar[0] - li.x * ai[0];
        accR[m] += lr.y * ar[1] - li.y * ai[1];
        accR[m] += lr.z * ar[2] - li.z * ai[2];
        accR[m] += lr.w * ar[3] - li.w * ai[3];
        accI[m] += lr.x * ai[0] + li.x * ar[0];
        accI[m] += lr.y * ai[1] + li.y * ar[1];
        accI[m] += lr.z * ai[2] + li.z * ar[2];
        accI[m] += lr.w * ai[3] + li.w * ar[3];
    }

    __shared__ float sred[8][8];   // [warp][q]
#pragma unroll
    for (int q = 0; q < 8; q++) {
        float x = (q < 4) ? accR[q] : accI[q - 4];
#pragma unroll
        for (int off = 16; off; off >>= 1) x += __shfl_xor_sync(0xffffffffu, x, off);
        if ((tid & 31) == 0) sred[tid >> 5][q] = x;
    }
    __syncthreads();
    if (tid < 8) {
        float x = 0.f;
#pragma unroll
        for (int w = 0; w < 8; w++) x += sred[w][tid];
        int m = tid & 3;
        if (tid < 4) g_rowR[(b * 4 + m) * N_ + i] = x;
        else         g_rowI[(b * 4 + m) * N_ + i] = x;
    }
}

// ============================================================
// Kernel 4: final einsums. 48KB static smem, 128 threads/block.
// Block = (og 0..3 [float4 over o], jl 0..31), o-slice oq (16 o),
// j-tile 32, one j per thread (JT=1).
//   smem: w slice (4m x 64c x 16o x r/i) = 32KB
//         X tile  (32j x 64c x r/i, XOR-swizzled) = 16KB
// Grid = 4 oq x 256 j-groups = 1024 blocks, 4 blocks/SM -> 16 warps/SM.
// ============================================================
#define FMA4(acc, s, v) \
    acc.x += (s) * (v).x; acc.y += (s) * (v).y; \
    acc.z += (s) * (v).z; acc.w += (s) * (v).w;

__global__ void __launch_bounds__(128, 4) k4_out(
    const float* __restrict__ Xr, const float* __restrict__ Xi,
    const float4* __restrict__ wr4, const float4* __restrict__ wi4,
    float* __restrict__ out)
{
    __shared__ float4 wr_s[KM * C_ * 4];    // 1024 f4 = 16 KB
    __shared__ float4 wi_s[KM * C_ * 4];    // 16 KB
    __shared__ float4 x_s[2][512];          // [ri][j*16 + (cq ^ (j&15))] = 16 KB
    // total = 49152 B = 48 KB exactly

    int tid = threadIdx.x;
    int og  = tid & 3;
    int jl  = tid >> 2;                     // 0..31
    int bx  = blockIdx.x;
    int jg  = bx & 255;
    int oq  = bx >> 8;
    int jbase = jg * 32;                    // global (b*N+j) base, same b within tile
    int b   = jbase >> 10;

    // ---- load w slice (coalesced 64B runs, from L2) ----
#pragma unroll
    for (int r = 0; r < 8; r++) {
        int e  = r * 128 + tid;             // 0..1023
        int mc = e >> 2, o2 = e & 3;
        wr_s[e] = wr4[mc * 16 + oq * 4 + o2];
        wi_s[e] = wi4[mc * 16 + oq * 4 + o2];
    }
    // ---- load X tile (fully coalesced), XOR-swizzled store ----
    {
        const float4* XrG = (const float4*)(Xr + (size_t)jbase * C_);
        const float4* XiG = (const float4*)(Xi + (size_t)jbase * C_);
#pragma unroll
        for (int r = 0; r < 4; r++) {
            int e  = r * 128 + tid;         // 0..511
            int j  = e >> 4, cq = e & 15;
            int si = (j << 4) | (cq ^ (j & 15));
            x_s[0][si] = XrG[e];
            x_s[1][si] = XiG[e];
        }
    }
    __syncthreads();

    // ---- main accumulation: one j per thread ----
    float4 PR[4], PI[4];
#pragma unroll
    for (int m = 0; m < 4; m++) {
        PR[m] = make_float4(0.f,0.f,0.f,0.f);
        PI[m] = make_float4(0.f,0.f,0.f,0.f);
    }
    int jm = jl & 15;

#pragma unroll
    for (int cq = 0; cq < 16; cq++) {
        float4 xr = x_s[0][(jl << 4) | (cq ^ jm)];
        float4 xi = x_s[1][(jl << 4) | (cq ^ jm)];
        const float* fxr = (const float*)&xr;
        const float* fxi = (const float*)&xi;
#pragma unroll
        for (int ci = 0; ci < 4; ci++) {
            int c = cq * 4 + ci;
            float a0 = fxr[ci], b0 = fxi[ci];
#pragma unroll
            for (int m = 0; m < 4; m++) {
                float4 wr = wr_s[((m << 6) + c) * 4 + og];
                float4 wi = wi_s[((m << 6) + c) * 4 + og];
                FMA4(PR[m], a0, wr);
                FMA4(PI[m], b0, wi);
            }
        }
    }

    // ---- combine over m with row vectors (L2 hits) and store ----
    {
        int jj = jbase + jl;                // global bn index
        int j  = jj & 1023;
        float4 re = make_float4(0.f,0.f,0.f,0.f);
        float4 im = make_float4(0.f,0.f,0.f,0.f);
#pragma unroll
        for (int m = 0; m < 4; m++) {
            float a  = g_rowR[(b * 4 + m) * N_ + j];
            float bi = g_rowI[(b * 4 + m) * N_ + j];
            re.x += a * PR[m].x - bi * PI[m].x;  re.y += a * PR[m].y - bi * PI[m].y;
            re.z += a * PR[m].z - bi * PI[m].z;  re.w += a * PR[m].w - bi * PI[m].w;
            im.x += bi * PR[m].x + a * PI[m].x;  im.y += bi * PR[m].y + a * PI[m].y;
            im.z += bi * PR[m].z + a * PI[m].z;  im.w += bi * PR[m].w + a * PI[m].w;
        }
        ((float4*)out)[jj * 16 + oq * 4 + og] = re;                 // real
        ((float4*)out)[BN * 16 + jj * 16 + oq * 4 + og] = im;       // imag
    }
}

// ============================================================
extern "C" void kernel_launch(void* const* d_in, const int* in_sizes, int n_in,
                              void* d_out, int out_size)
{
    const float* Xr  = (const float*)d_in[0];
    const float* Xi  = (const float*)d_in[1];
    const float* Lr  = (const float*)d_in[2];
    const float* Li  = (const float*)d_in[3];
    const float* wr  = (const float*)d_in[4];
    const float* wi  = (const float*)d_in[5];
    const float* awr = (const float*)d_in[6];
    const float* awi = (const float*)d_in[7];
    const float* abr = (const float*)d_in[8];
    const float* abi = (const float*)d_in[9];
    const float* par = (const float*)d_in[10];
    const float* pai = (const float*)d_in[11];
    float* out = (float*)d_out;

    k1_proj  <<<BN / 8, 256>>>(Xr, Xi, awr, awi, abr, abi);
    k2_sumexp<<<BN,     128>>>(par, pai);
    k3_main  <<<BN,     256>>>(Lr, Li, par, pai);
    k4_out   <<<4 * 256, 128>>>(Xr, Xi, (const float4*)wr, (const float4*)wi, out);
}

// round 6
// speedup vs baseline: 1.1129x; 1.1129x over previous
#include <cuda_runtime.h>

// Problem constants
#define B_  8
#define N_  1024
#define C_  64
#define O_  64
#define KM  4          // K+1
#define BN  (B_*N_)    // 8192

// -------- device scratch (no allocations allowed) --------
__device__ float g_sRi[BN], g_sIi[BN], g_sRj[BN], g_sIj[BN];
__device__ float g_rsum[BN];                 // 1 / sum_i exp(mag[b,i,j]) per (b,j)
__device__ float g_rowR[KM*BN], g_rowI[KM*BN];  // (b*4+m)*N + i

// ============================================================
// Kernel 1: per-(b,n) attention projections. One warp per (b,n).
// ============================================================
__global__ void __launch_bounds__(256) k1_proj(
    const float* __restrict__ Xr, const float* __restrict__ Xi,
    const float* __restrict__ awr, const float* __restrict__ awi,
    const float* __restrict__ abr, const float* __restrict__ abi)
{
    int warp = (blockIdx.x * blockDim.x + threadIdx.x) >> 5;
    int lane = threadIdx.x & 31;
    if (warp >= BN) return;
    const float* xr = Xr + warp * C_;
    const float* xi = Xi + warp * C_;
    float sRi = 0.f, sIi = 0.f, sRj = 0.f, sIj = 0.f;
#pragma unroll
    for (int t = 0; t < 2; t++) {
        int c = lane + t * 32;
        float a = xr[c], b = xi[c];
        float wri = awr[c],      wii = awi[c];
        float wrj = awr[C_ + c], wij = awi[C_ + c];
        sRi += a * wri - b * wii;
        sIi += a * wii + b * wri;
        sRj += a * wrj - b * wij;
        sIj += a * wij + b * wrj;
    }
#pragma unroll
    for (int off = 16; off; off >>= 1) {
        sRi += __shfl_xor_sync(0xffffffffu, sRi, off);
        sIi += __shfl_xor_sync(0xffffffffu, sIi, off);
        sRj += __shfl_xor_sync(0xffffffffu, sRj, off);
        sIj += __shfl_xor_sync(0xffffffffu, sIj, off);
    }
    if (lane == 0) {
        g_sRi[warp] = sRi + abr[0];
        g_sIi[warp] = sIi + abi[0];
        g_sRj[warp] = sRj;
        g_sIj[warp] = sIj;
    }
}

// ============================================================
// Kernel 2: softmax denominator per (b,j): sum over i of exp(mag).
// mag is bounded (<~8) so no max-subtraction needed (identical math).
// ============================================================
__global__ void __launch_bounds__(128) k2_sumexp(
    const float* __restrict__ par, const float* __restrict__ pai)
{
    int bj = blockIdx.x;          // b*N + j
    int b  = bj >> 10;
    float sRj = g_sRj[bj], sIj = g_sIj[bj];
    float a_r = par[0], a_i = pai[0];
    const float* sRi = g_sRi + (b << 10);
    const float* sIi = g_sIi + (b << 10);
    float acc = 0.f;
#pragma unroll
    for (int t = 0; t < N_ / 128; t++) {
        int i = threadIdx.x + t * 128;
        float sr = sRi[i] + sRj;
        float si = sIi[i] + sIj;
        float pr = sr >= 0.f ? sr : a_r * sr;
        float pi = si >= 0.f ? si : a_i * si;
        float r2 = pr * pr + pi * pi;
        float inv = rsqrtf(fmaxf(r2, 1e-30f));
        float mag = r2 * inv;
        acc += __expf(mag);
    }
    __shared__ float sred[4];
#pragma unroll
    for (int off = 16; off; off >>= 1) acc += __shfl_xor_sync(0xffffffffu, acc, off);
    if ((threadIdx.x & 31) == 0) sred[threadIdx.x >> 5] = acc;
    __syncthreads();
    if (threadIdx.x == 0) {
        float t = sred[0] + sred[1] + sred[2] + sred[3];
        g_rsum[bj] = 1.f / t;
    }
}

// ============================================================
// Kernel 3 (dominant, HBM-bound): one block per (b,i) row.
// Streams L_real/L_imag exactly once (268 MB) -> rowR/rowI.
// ============================================================
__global__ void __launch_bounds__(256) k3_main(
    const float* __restrict__ Lr, const float* __restrict__ Li,
    const float* __restrict__ par, const float* __restrict__ pai)
{
    int bi = blockIdx.x;          // b*N + i
    int b  = bi >> 10;
    int i  = bi & 1023;
    int tid = threadIdx.x;
    int j0 = tid * 4;

    float sRi = g_sRi[bi], sIi = g_sIi[bi];
    float a_r = par[0], a_i = pai[0];

    const int bj0 = (b << 10) + j0;
    float4 sRj4 = *(const float4*)(g_sRj + bj0);
    float4 sIj4 = *(const float4*)(g_sIj + bj0);
    float4 rs4  = *(const float4*)(g_rsum + bj0);
    float sRjv[4] = {sRj4.x, sRj4.y, sRj4.z, sRj4.w};
    float sIjv[4] = {sIj4.x, sIj4.y, sIj4.z, sIj4.w};
    float rsv [4] = {rs4.x,  rs4.y,  rs4.z,  rs4.w };

    float ar[4], ai[4];
#pragma unroll
    for (int k = 0; k < 4; k++) {
        float sr = sRi + sRjv[k];
        float si = sIi + sIjv[k];
        float pr = sr >= 0.f ? sr : a_r * sr;
        float pi = si >= 0.f ? si : a_i * si;
        float r2 = pr * pr + pi * pi;
        float inv = rsqrtf(fmaxf(r2, 1e-30f));
        float mag = r2 * inv;
        float e = __expf(mag);
        float sc = e * inv * rsv[k];
        ar[k] = sc * pr;
        ai[k] = sc * pi;
    }

    float accR[4], accI[4];
#pragma unroll
    for (int m = 0; m < 4; m++) { accR[m] = 0.f; accI[m] = 0.f; }

#pragma unroll
    for (int m = 0; m < 4; m++) {
        size_t base = ((size_t)((b * 4 + m) * N_ + i)) * N_ + j0;
        float4 lr = *(const float4*)(Lr + base);
        float4 li = *(const float4*)(Li + base);
        accR[m] += lr.x * ar[0] - li.x * ai[0];
        accR[m] += lr.y * ar[1] - li.y * ai[1];
        accR[m] += lr.z * ar[2] - li.z * ai[2];
        accR[m] += lr.w * ar[3] - li.w * ai[3];
        accI[m] += lr.x * ai[0] + li.x * ar[0];
        accI[m] += lr.y * ai[1] + li.y * ar[1];
        accI[m] += lr.z * ai[2] + li.z * ar[2];
        accI[m] += lr.w * ai[3] + li.w * ar[3];
    }

    __shared__ float sred[8][8];   // [warp][q]
#pragma unroll
    for (int q = 0; q < 8; q++) {
        float x = (q < 4) ? accR[q] : accI[q - 4];
#pragma unroll
        for (int off = 16; off; off >>= 1) x += __shfl_xor_sync(0xffffffffu, x, off);
        if ((tid & 31) == 0) sred[tid >> 5][q] = x;
    }
    __syncthreads();
    if (tid < 8) {
        float x = 0.f;
#pragma unroll
        for (int w = 0; w < 8; w++) x += sred[w][tid];
        int m = tid & 3;
        if (tid < 4) g_rowR[(b * 4 + m) * N_ + i] = x;
        else         g_rowI[(b * 4 + m) * N_ + i] = x;
    }
}

// ============================================================
// Kernel 4: final einsums. 48KB static smem, 128 threads/block.
// Block = (og 0..3, jl 0..31), o-slice 16 (oq), j-tile 64, JT=2.
//   smem: w slice (4m x 64c x 16o x r/i)          = 32 KB resident
//         X phase double-buffer (64j x 16c x r/i) = 2 x 8 KB
// X streamed in 4 c-phases; loads issued before each phase's compute.
// Grid = 4 oq x 128 jg = 512 blocks, 4/SM -> 16 warps/SM, ratio 8.
// ============================================================
#define FMA4(acc, s, v) \
    acc.x += (s) * (v).x; acc.y += (s) * (v).y; \
    acc.z += (s) * (v).z; acc.w += (s) * (v).w;

// swizzled index within an 8KB phase buffer: j in [0,64), q in [0,4)
#define XSW(j, q) (((j) << 2) | ((q) ^ ((j) & 3) ^ (((j) >> 2) & 3)))

__global__ void __launch_bounds__(128, 4) k4_out(
    const float* __restrict__ Xr, const float* __restrict__ Xi,
    const float4* __restrict__ wr4, const float4* __restrict__ wi4,
    float* __restrict__ out)
{
    __shared__ float4 wr_s[KM * C_ * 4];     // (m*64+c)*4+og : 16 KB
    __shared__ float4 wi_s[KM * C_ * 4];     // 16 KB
    __shared__ float4 x_s[2][2][256];        // [buf][ri][XSW(j,q)] : 16 KB

    int tid = threadIdx.x;
    int og  = tid & 3;
    int jl  = tid >> 2;                      // 0..31
    int bx  = blockIdx.x;
    int jg  = bx & 127;
    int oq  = bx >> 7;                       // 0..3
    int jbase = jg * 64;                     // same b within 64-j tile
    int b   = jbase >> 10;

    const float4* XrG = (const float4*)Xr + (size_t)jbase * 16;
    const float4* XiG = (const float4*)Xi + (size_t)jbase * 16;

    // ---- w slice load (resident) ----
#pragma unroll
    for (int r = 0; r < 8; r++) {
        int e  = r * 128 + tid;              // 0..1023
        int mc = e >> 2, o2 = e & 3;
        wr_s[e] = wr4[mc * 16 + oq * 4 + o2];
        wi_s[e] = wi4[mc * 16 + oq * 4 + o2];
    }

    // ---- X phase 0 load ----
#pragma unroll
    for (int r = 0; r < 2; r++) {
        int e = r * 128 + tid;               // 0..255
        int j = e >> 2, q = e & 3;
        int si = XSW(j, q);
        x_s[0][0][si] = XrG[j * 16 + q];
        x_s[0][1][si] = XiG[j * 16 + q];
    }
    __syncthreads();

    float4 PR0[4], PI0[4], PR1[4], PI1[4];
#pragma unroll
    for (int m = 0; m < 4; m++) {
        PR0[m] = make_float4(0.f,0.f,0.f,0.f); PI0[m] = make_float4(0.f,0.f,0.f,0.f);
        PR1[m] = make_float4(0.f,0.f,0.f,0.f); PI1[m] = make_float4(0.f,0.f,0.f,0.f);
    }

    int j0 = jl, j1 = jl + 32;

#pragma unroll
    for (int p = 0; p < 4; p++) {
        int buf = p & 1;
        // issue next phase's loads first (latency hidden under compute)
        if (p < 3) {
            int nb = buf ^ 1;
#pragma unroll
            for (int r = 0; r < 2; r++) {
                int e = r * 128 + tid;
                int j = e >> 2, q = e & 3;
                int si = XSW(j, q);
                x_s[nb][0][si] = XrG[j * 16 + (p + 1) * 4 + q];
                x_s[nb][1][si] = XiG[j * 16 + (p + 1) * 4 + q];
            }
        }
        // compute this phase: c in [p*16, p*16+16)
#pragma unroll
        for (int q = 0; q < 4; q++) {
            float4 xr0 = x_s[buf][0][XSW(j0, q)];
            float4 xi0 = x_s[buf][1][XSW(j0, q)];
            float4 xr1 = x_s[buf][0][XSW(j1, q)];
            float4 xi1 = x_s[buf][1][XSW(j1, q)];
            const float* fxr0 = (const float*)&xr0;
            const float* fxi0 = (const float*)&xi0;
            const float* fxr1 = (const float*)&xr1;
            const float* fxi1 = (const float*)&xi1;
#pragma unroll
            for (int ci = 0; ci < 4; ci++) {
                int c = p * 16 + q * 4 + ci;
                float a0 = fxr0[ci], b0 = fxi0[ci];
                float a1 = fxr1[ci], b1 = fxi1[ci];
#pragma unroll
                for (int m = 0; m < 4; m++) {
                    float4 wr = wr_s[((m << 6) + c) * 4 + og];
                    float4 wi = wi_s[((m << 6) + c) * 4 + og];
                    FMA4(PR0[m], a0, wr);
                    FMA4(PI0[m], b0, wi);
                    FMA4(PR1[m], a1, wr);
                    FMA4(PI1[m], b1, wi);
                }
            }
        }
        __syncthreads();
    }

    // ---- combine over m with row vectors and store ----
#pragma unroll
    for (int jt = 0; jt < 2; jt++) {
        int jj = jbase + jl + jt * 32;       // global bn index
        int j  = jj & 1023;
        float4 re = make_float4(0.f,0.f,0.f,0.f);
        float4 im = make_float4(0.f,0.f,0.f,0.f);
#pragma unroll
        for (int m = 0; m < 4; m++) {
            float a  = g_rowR[(b * 4 + m) * N_ + j];
            float bi = g_rowI[(b * 4 + m) * N_ + j];
            float4 pr = jt ? PR1[m] : PR0[m];
            float4 pi = jt ? PI1[m] : PI0[m];
            re.x += a * pr.x - bi * pi.x;  re.y += a * pr.y - bi * pi.y;
            re.z += a * pr.z - bi * pi.z;  re.w += a * pr.w - bi * pi.w;
            im.x += bi * pr.x + a * pi.x;  im.y += bi * pr.y + a * pi.y;
            im.z += bi * pr.z + a * pi.z;  im.w += bi * pr.w + a * pi.w;
        }
        ((float4*)out)[jj * 16 + oq * 4 + og] = re;                 // real
        ((float4*)out)[BN * 16 + jj * 16 + oq * 4 + og] = im;       // imag
    }
}

// ============================================================
extern "C" void kernel_launch(void* const* d_in, const int* in_sizes, int n_in,
                              void* d_out, int out_size)
{
    const float* Xr  = (const float*)d_in[0];
    const float* Xi  = (const float*)d_in[1];
    const float* Lr  = (const float*)d_in[2];
    const float* Li  = (const float*)d_in[3];
    const float* wr  = (const float*)d_in[4];
    const float* wi  = (const float*)d_in[5];
    const float* awr = (const float*)d_in[6];
    const float* awi = (const float*)d_in[7];
    const float* abr = (const float*)d_in[8];
    const float* abi = (const float*)d_in[9];
    const float* par = (const float*)d_in[10];
    const float* pai = (const float*)d_in[11];
    float* out = (float*)d_out;

    k1_proj  <<<BN / 8, 256>>>(Xr, Xi, awr, awi, abr, abi);
    k2_sumexp<<<BN,     128>>>(par, pai);
    k3_main  <<<BN,     256>>>(Lr, Li, par, pai);
    k4_out   <<<4 * 128, 128>>>(Xr, Xi, (const float4*)wr, (const float4*)wi, out);
}